// round 15
// baseline (speedup 1.0000x reference)
#include <cuda_runtime.h>
#include <cuda_bf16.h>
#include <cuda_fp16.h>
#include <math.h>
#include <stdint.h>

#define BB 32
#define TT 128
#define DD 128
#define HH 8
#define HD 16
#define LL 4
#define VV 50257
#define BT (BB * TT)       // 4096
#define DFF (4 * DD)       // 512
#define NBLK 393                 // ceil(VV / 128)
#define NPAD (NBLK * 128)        // 50304

// ---------------- scratch ----------------
__device__ float g_x[BT * DD];
__device__ float g_qkv[BT * 384];
__device__ float g_part[(size_t)BT * NBLK];
__device__ float g_nll[BT];
__device__ __half g_t1h[BT * DD],  g_t1l[BT * DD];    // LN outputs (and final LN)
__device__ __half g_oh[BT * DD],   g_ol[BT * DD];     // attn output
__device__ __half g_t2h[BT * DFF], g_t2l[BT * DFF];   // mlp hidden
__device__ __half g_bh[(size_t)NPAD * DD];
// body weights, n-major [N][K] fp16 hi/lo
__device__ __half g_wqkvh[LL * 384 * DD], g_wqkvl[LL * 384 * DD];
__device__ __half g_wph[LL * DD * DD],   g_wpl[LL * DD * DD];
__device__ __half g_w1h[LL * DFF * DD],  g_w1l[LL * DFF * DD];
__device__ __half g_w2h[LL * DD * DFF],  g_w2l[LL * DD * DFF];

// ---------------- helpers ----------------
__device__ __forceinline__ uint32_t smem_u32(const void* p) {
    uint32_t a;
    asm("{ .reg .u64 t; cvta.to.shared.u64 t, %1; cvt.u32.u64 %0, t; }" : "=r"(a) : "l"(p));
    return a;
}
__device__ __forceinline__ void mma16816(float* c, const uint32_t* a,
                                         uint32_t b0, uint32_t b1) {
    asm volatile(
        "mma.sync.aligned.m16n8k16.row.col.f32.f16.f16.f32 "
        "{%0,%1,%2,%3}, {%4,%5,%6,%7}, {%8,%9}, {%0,%1,%2,%3};"
        : "+f"(c[0]), "+f"(c[1]), "+f"(c[2]), "+f"(c[3])
        : "r"(a[0]), "r"(a[1]), "r"(a[2]), "r"(a[3]), "r"(b0), "r"(b1));
}
__device__ __forceinline__ void ldsm4(uint32_t* r, uint32_t addr) {
    asm volatile("ldmatrix.sync.aligned.m8n8.x4.shared.b16 {%0,%1,%2,%3}, [%4];"
                 : "=r"(r[0]), "=r"(r[1]), "=r"(r[2]), "=r"(r[3]) : "r"(addr));
}
__device__ __forceinline__ void stcs(float* p, float v) {
    asm volatile("st.global.cs.f32 [%0], %1;" :: "l"(p), "f"(v) : "memory");
}

// ---------------- embedding ----------------
__global__ void embed_k(const int* __restrict__ idx,
                        const float* __restrict__ tok,
                        const float* __restrict__ pos) {
    int m = blockIdx.x;
    int d = threadIdx.x;
    int t = m & (TT - 1);
    g_x[m * DD + d] = tok[(size_t)idx[m] * DD + d] + pos[t * DD + d];
}

// ---------------- qkv weights [L,H,D,HD] -> n-major [L][384][128] fp16 hi/lo ----------------
__global__ void cvtwqkv_k(const float* __restrict__ wq,
                          const float* __restrict__ wk,
                          const float* __restrict__ wv) {
    int o = blockIdx.x * 256 + threadIdx.x;
    if (o >= LL * 384 * DD) return;
    int l = o / (384 * DD);
    int rem = o % (384 * DD);
    int n = rem >> 7, d = rem & 127;
    int which = n >> 7;
    int nn = n & 127;
    int h = nn >> 4, e = nn & 15;
    const float* W = (which == 0) ? wq : (which == 1) ? wk : wv;
    float x = W[(((size_t)l * HH + h) * DD + d) * HD + e];
    __half hi = __float2half(x);
    g_wqkvh[o] = hi;
    g_wqkvl[o] = __float2half(x - __half2float(hi));
}

// ---------------- generic weight transpose-convert: W[l][K][N] -> [l][N][K] hi/lo ----------------
__global__ void cvtw_k(const float* __restrict__ W, __half* __restrict__ oh,
                       __half* __restrict__ ol, int K, int N) {
    __shared__ float t[32][33];
    int l = blockIdx.z;
    const float* Wl = W + (size_t)l * K * N;
    __half* ohl = oh + (size_t)l * N * K;
    __half* oll = ol + (size_t)l * N * K;
    int n0 = blockIdx.x * 32, k0 = blockIdx.y * 32;
    int tx = threadIdx.x, ty = threadIdx.y;  // 32 x 8
    for (int i = ty; i < 32; i += 8)
        t[i][tx] = Wl[(size_t)(k0 + i) * N + n0 + tx];
    __syncthreads();
    for (int i = ty; i < 32; i += 8) {
        int n = n0 + i, k = k0 + tx;
        float x = t[tx][i];
        __half hi = __float2half(x);
        ohl[(size_t)n * K + k] = hi;
        oll[(size_t)n * K + k] = __float2half(x - __half2float(hi));
    }
}

// ---------------- LN fused with fp16 hi/lo split ----------------
__global__ void lnsplit_k(const float* __restrict__ in,
                          const float* __restrict__ gam, const float* __restrict__ bet,
                          __half* __restrict__ oh, __half* __restrict__ ol) {
    __shared__ float red[4];
    int m = blockIdx.x, d = threadIdx.x;
    int i = m * DD + d;
    float x = in[i];
    float s = x;
#pragma unroll
    for (int o = 16; o > 0; o >>= 1) s += __shfl_xor_sync(0xffffffffu, s, o);
    if ((d & 31) == 0) red[d >> 5] = s;
    __syncthreads();
    float mean = (red[0] + red[1] + red[2] + red[3]) * (1.0f / DD);
    __syncthreads();
    float c = x - mean;
    float cs = c * c;
#pragma unroll
    for (int o = 16; o > 0; o >>= 1) cs += __shfl_xor_sync(0xffffffffu, cs, o);
    if ((d & 31) == 0) red[d >> 5] = cs;
    __syncthreads();
    float var = (red[0] + red[1] + red[2] + red[3]) * (1.0f / DD);
    float y = c * rsqrtf(var + 1e-5f) * gam[d] + bet[d];
    __half hi = __float2half(y);
    oh[i] = hi;
    ol[i] = __float2half(y - __half2float(hi));
}

// ---------------- attention (fp32 in, fp16 hi/lo out) ----------------
__global__ void attn_k() {
    int b = blockIdx.x / HH;
    int h = blockIdx.x % HH;
    int t = threadIdx.x;
    __shared__ float ks[TT][HD];
    __shared__ float vs[TT][HD];
    const float* rowp = g_qkv + (size_t)(b * TT + t) * 384 + h * HD;
#pragma unroll
    for (int e = 0; e < HD; e++) {
        ks[t][e] = rowp[128 + e];
        vs[t][e] = rowp[256 + e];
    }
    __syncthreads();
    float q[HD];
#pragma unroll
    for (int e = 0; e < HD; e++) q[e] = rowp[e];

    const float scale = 0.08838834764831845f;  // 1/sqrt(128)
    float mrun = -1e30f, lrun = 0.0f;
    float acc[HD];
#pragma unroll
    for (int e = 0; e < HD; e++) acc[e] = 0.0f;
    for (int s = 0; s <= t; s++) {
        float d = 0.0f;
#pragma unroll
        for (int e = 0; e < HD; e++) d += q[e] * ks[s][e];
        d *= scale;
        float mn = fmaxf(mrun, d);
        float corr = __expf(mrun - mn);
        float p = __expf(d - mn);
        lrun = lrun * corr + p;
#pragma unroll
        for (int e = 0; e < HD; e++) acc[e] = acc[e] * corr + p * vs[s][e];
        mrun = mn;
    }
    float inv = 1.0f / lrun;
    size_t base = (size_t)(b * TT + t) * DD + h * HD;
#pragma unroll
    for (int e = 0; e < HD; e += 2) {
        float v0 = acc[e] * inv, v1 = acc[e + 1] * inv;
        __half h0 = __float2half(v0), h1 = __float2half(v1);
        *(__half2*)&g_oh[base + e] = __halves2half2(h0, h1);
        *(__half2*)&g_ol[base + e] = __halves2half2(
            __float2half(v0 - __half2float(h0)), __float2half(v1 - __half2float(h1)));
    }
}

// ---------------- HMMA body GEMM: 64x64 tile, 4 warps, fp16 hi/lo 3-term ----------------
// A given pre-split as hi/lo fp16 [M][K]. flags: 1=bias, 2=relu, 4=fp32 residual out, 8=fp16 hi/lo out
#define HG_AH 0
#define HG_AL (HG_AH + 17408)
#define HG_BH (HG_AL + 17408)
#define HG_BL (HG_BH + 17408)
#define HG_SMEM (HG_BL + 17408)       // 69632 bytes

__global__ void __launch_bounds__(128) hgemm_k(
    const __half* __restrict__ Agh, const __half* __restrict__ Agl,
    const __half* __restrict__ Bh, const __half* __restrict__ Bl,
    const float* __restrict__ bias, const float* __restrict__ Rres,
    float* __restrict__ C, __half* __restrict__ Ch, __half* __restrict__ Cl,
    int M, int N, int K, int flags) {
    extern __shared__ __align__(16) char smem[];
    __half* Ahs = (__half*)(smem + HG_AH);
    __half* Als = (__half*)(smem + HG_AL);
    __half* Bhs = (__half*)(smem + HG_BH);
    __half* Bls = (__half*)(smem + HG_BL);
    uint32_t sb = smem_u32(smem);

    int tid = threadIdx.x, wid = tid >> 5, lane = tid & 31;
    int bm0 = blockIdx.y * 64, bn0 = blockIdx.x * 64;
    int wm = (wid >> 1) * 32, wn = (wid & 1) * 32;
    int g = lane >> 2, t4 = lane & 3;

    float acc[2][4][4];
#pragma unroll
    for (int i = 0; i < 2; i++)
#pragma unroll
        for (int j = 0; j < 4; j++)
#pragma unroll
            for (int q = 0; q < 4; q++) acc[i][j][q] = 0.0f;

    int lr = lane & 15, lk = lane >> 4;
    uint32_t aHb = sb + HG_AH + (uint32_t)((wm + lr) * 272 + lk * 16);
    uint32_t aLb = sb + HG_AL + (uint32_t)((wm + lr) * 272 + lk * 16);
    uint32_t bHb = sb + HG_BH + (uint32_t)((wn + lr) * 272 + lk * 16);
    uint32_t bLb = sb + HG_BL + (uint32_t)((wn + lr) * 272 + lk * 16);

    for (int kc = 0; kc < K; kc += 128) {
        if (kc) __syncthreads();
        {
            const uint4* ahp = (const uint4*)Agh;
            const uint4* alp = (const uint4*)Agl;
            const uint4* bhp = (const uint4*)Bh;
            const uint4* blp = (const uint4*)Bl;
            int krow = K >> 3, kco = kc >> 3;
            for (int i = tid; i < 1024; i += 128) {
                int row = i >> 4, cb = i & 15;
                size_t ga = (size_t)(bm0 + row) * krow + kco + cb;
                size_t gb2 = (size_t)(bn0 + row) * krow + kco + cb;
                *(uint4*)&Ahs[row * 136 + cb * 8] = ahp[ga];
                *(uint4*)&Als[row * 136 + cb * 8] = alp[ga];
                *(uint4*)&Bhs[row * 136 + cb * 8] = bhp[gb2];
                *(uint4*)&Bls[row * 136 + cb * 8] = blp[gb2];
            }
        }
        __syncthreads();
#pragma unroll
        for (int ks = 0; ks < 8; ks++) {
            uint32_t off = (uint32_t)ks * 32;
            uint32_t ah0[4], ah1[4], al0[4], al1[4];
            uint32_t bh0[4], bh1[4], bl0[4], bl1[4];
            ldsm4(ah0, aHb + off); ldsm4(ah1, aHb + 16 * 272 + off);
            ldsm4(al0, aLb + off); ldsm4(al1, aLb + 16 * 272 + off);
            ldsm4(bh0, bHb + off); ldsm4(bh1, bHb + 16 * 272 + off);
            ldsm4(bl0, bLb + off); ldsm4(bl1, bLb + 16 * 272 + off);
#pragma unroll
            for (int i = 0; i < 2; i++) {
                const uint32_t* ahi = i ? ah1 : ah0;
                const uint32_t* alo = i ? al1 : al0;
#pragma unroll
                for (int j = 0; j < 4; j++) {
                    const uint32_t* bh = (j < 2) ? bh0 : bh1;
                    const uint32_t* bl = (j < 2) ? bl0 : bl1;
                    uint32_t b0h = bh[j & 1], b1h = bh[(j & 1) + 2];
                    uint32_t b0l = bl[j & 1], b1l = bl[(j & 1) + 2];
                    mma16816(acc[i][j], ahi, b0h, b1h);
                    mma16816(acc[i][j], alo, b0h, b1h);
                    mma16816(acc[i][j], ahi, b0l, b1l);
                }
            }
        }
    }

    // epilogue
#pragma unroll
    for (int i = 0; i < 2; i++) {
#pragma unroll
        for (int j = 0; j < 4; j++) {
            int col = bn0 + wn + j * 8 + 2 * t4;
            float bx = 0.0f, by = 0.0f;
            if (flags & 1) { bx = bias[col]; by = bias[col + 1]; }
            int r0 = bm0 + wm + i * 16 + g;
            float2 v0 = make_float2(acc[i][j][0] + bx, acc[i][j][1] + by);
            float2 v1 = make_float2(acc[i][j][2] + bx, acc[i][j][3] + by);
            if (flags & 2) {
                v0.x = fmaxf(v0.x, 0.f); v0.y = fmaxf(v0.y, 0.f);
                v1.x = fmaxf(v1.x, 0.f); v1.y = fmaxf(v1.y, 0.f);
            }
            if (flags & 8) {
                __half h0 = __float2half(v0.x), h1 = __float2half(v0.y);
                *(__half2*)&Ch[(size_t)r0 * N + col] = __halves2half2(h0, h1);
                *(__half2*)&Cl[(size_t)r0 * N + col] = __halves2half2(
                    __float2half(v0.x - __half2float(h0)),
                    __float2half(v0.y - __half2float(h1)));
                __half h2 = __float2half(v1.x), h3 = __float2half(v1.y);
                *(__half2*)&Ch[(size_t)(r0 + 8) * N + col] = __halves2half2(h2, h3);
                *(__half2*)&Cl[(size_t)(r0 + 8) * N + col] = __halves2half2(
                    __float2half(v1.x - __half2float(h2)),
                    __float2half(v1.y - __half2float(h3)));
            } else {
                if (flags & 4) {
                    float2 r = *(const float2*)&Rres[(size_t)r0 * N + col];
                    v0.x += r.x; v0.y += r.y;
                    r = *(const float2*)&Rres[(size_t)(r0 + 8) * N + col];
                    v1.x += r.x; v1.y += r.y;
                }
                *(float2*)&C[(size_t)r0 * N + col] = v0;
                *(float2*)&C[(size_t)(r0 + 8) * N + col] = v1;
            }
        }
    }
}

// lm_w [128, V] -> transposed padded [NPAD, 128] fp16 (n-major)
__global__ void cvtb_k(const float* __restrict__ lm_w) {
    __shared__ float t[32][33];
    int n0 = blockIdx.x * 32, k0 = blockIdx.y * 32;
    int tx = threadIdx.x, ty = threadIdx.y;  // 32 x 8
    for (int i = ty; i < 32; i += 8) {
        int n = n0 + tx, k = k0 + i;
        t[i][tx] = (n < VV) ? lm_w[(size_t)k * VV + n] : 0.0f;
    }
    __syncthreads();
    for (int i = ty; i < 32; i += 8) {
        int n = n0 + i, k = k0 + tx;
        g_bh[(size_t)n * DD + k] = __float2half(t[tx][i]);
    }
}

// ---------------- HMMA LM head (pure fp16, ldmatrix, staged coalesced epilogue) ----------------
#define PADH 136
#define ROWB (PADH * 2)                    // 272 bytes per row
#define AH_OFF 0
#define BH_OFF (128 * ROWB)                // 34816
#define BIAS_OFF (2 * 128 * ROWB)          // 69632
#define LM_SMEM (BIAS_OFF + 128 * 4)       // 70144

__global__ void __launch_bounds__(256, 3) lmhead_k(
    const float* __restrict__ bias, float* __restrict__ C) {
    extern __shared__ __align__(16) char smem[];
    uint32_t smem_base = smem_u32(smem);
    int tid = threadIdx.x;
    int wid = tid >> 5;
    int lane = tid & 31;
    int g = lane >> 2;
    int t4 = lane & 3;
    int bm0 = blockIdx.x * 128;
    int bn0 = blockIdx.y * 128;
    int wm = (wid >> 1) * 32;
    int wn = (wid & 1) * 64;

    {
        const uint4* gah = (const uint4*)g_t1h;
        const uint4* gbh = (const uint4*)g_bh;
#pragma unroll
        for (int i = tid; i < 2048; i += 256) {
            int row = i >> 4, cb = i & 15;
            uint32_t so = (uint32_t)(row * ROWB + cb * 16);
            *(uint4*)(smem + AH_OFF + so) = gah[(size_t)(bm0 + row) * 16 + cb];
            *(uint4*)(smem + BH_OFF + so) = gbh[(size_t)(bn0 + row) * 16 + cb];
        }
        float* bs = (float*)(smem + BIAS_OFF);
        if (tid < 128) {
            int c = bn0 + tid;
            bs[tid] = (c < VV) ? bias[c] : 0.0f;
        }
    }
    __syncthreads();

    float acc[2][8][4];
#pragma unroll
    for (int i = 0; i < 2; i++)
#pragma unroll
        for (int j = 0; j < 8; j++)
#pragma unroll
            for (int q = 0; q < 4; q++) acc[i][j][q] = 0.0f;

    int lr = lane & 15;
    int lk = lane >> 4;
    uint32_t abase = smem_base + AH_OFF + (uint32_t)((wm + lr) * ROWB + lk * 16);
    uint32_t bbase[4];
#pragma unroll
    for (int jp = 0; jp < 4; jp++)
        bbase[jp] = smem_base + BH_OFF + (uint32_t)((wn + jp * 16 + lr) * ROWB + lk * 16);

#pragma unroll
    for (int ks = 0; ks < 8; ks++) {
        uint32_t off = (uint32_t)ks * 32;
        uint32_t a0[4], a1[4];
        ldsm4(a0, abase + off);
        ldsm4(a1, abase + (uint32_t)(16 * ROWB) + off);
#pragma unroll
        for (int jp = 0; jp < 4; jp++) {
            uint32_t r[4];
            ldsm4(r, bbase[jp] + off);
            mma16816(acc[0][2 * jp],     a0, r[0], r[2]);
            mma16816(acc[0][2 * jp + 1], a0, r[1], r[3]);
            mma16816(acc[1][2 * jp],     a1, r[0], r[2]);
            mma16816(acc[1][2 * jp + 1], a1, r[1], r[3]);
        }
    }

    // ---- stage accumulators to smem (A/B tiles dead; bias region preserved) ----
    __syncthreads();
    float* stage = (float*)smem;  // 128 rows x 136 floats = 69632 bytes
#pragma unroll
    for (int i = 0; i < 2; i++) {
#pragma unroll
        for (int half = 0; half < 2; half++) {
            int r = wm + i * 16 + half * 8 + g;
#pragma unroll
            for (int j = 0; j < 8; j++) {
                int c = wn + j * 8 + 2 * t4;
                *(float2*)&stage[r * 136 + c] =
                    make_float2(acc[i][j][half * 2], acc[i][j][half * 2 + 1]);
            }
        }
    }
    __syncthreads();

    // ---- drain: coalesced per-row streaming stores + fused sum(exp) ----
    const float* bs = (const float*)(smem + BIAS_OFF);
    for (int rr = 0; rr < 16; rr++) {
        int r = wid * 16 + rr;
        int grow = bm0 + r;
        float* crow = C + (size_t)grow * VV + bn0;
        float s = 0.0f;
#pragma unroll
        for (int p = 0; p < 4; p++) {
            int col = p * 32 + lane;
            float v = stage[r * 136 + col] + bs[col];
            if (bn0 + col < VV) {
                stcs(crow + col, v);
                s += __expf(v);
            }
        }
#pragma unroll
        for (int o = 16; o > 0; o >>= 1) s += __shfl_xor_sync(0xffffffffu, s, o);
        if (lane == 0) g_part[(size_t)grow * NBLK + blockIdx.y] = s;
    }
}

// ---------------- NLL from partials ----------------
__global__ void nllred_k(const float* __restrict__ logits, const int* __restrict__ tgt) {
    int r = blockIdx.x;
    int tid = threadIdx.x;  // 128
    float s = 0.0f;
    for (int c = tid; c < NBLK; c += 128) s += g_part[(size_t)r * NBLK + c];
    __shared__ float red[4];
#pragma unroll
    for (int o = 16; o > 0; o >>= 1) s += __shfl_xor_sync(0xffffffffu, s, o);
    if ((tid & 31) == 0) red[tid >> 5] = s;
    __syncthreads();
    if (tid == 0) {
        float tot = red[0] + red[1] + red[2] + red[3];
        g_nll[r] = logf(tot) - logits[(size_t)r * VV + tgt[r]];
    }
}

__global__ void loss_k(float* __restrict__ out) {
    __shared__ float accs[256];
    float s = 0.0f;
    for (int i = threadIdx.x; i < BT; i += 256) s += g_nll[i];
    accs[threadIdx.x] = s;
    __syncthreads();
    for (int o = 128; o > 0; o >>= 1) {
        if (threadIdx.x < o) accs[threadIdx.x] += accs[threadIdx.x + o];
        __syncthreads();
    }
    if (threadIdx.x == 0) out[0] = accs[0] * (1.0f / BT);
}

// ---------------- host launcher ----------------
static void launch_hgemm(const __half* Ah, const __half* Al,
                         const __half* Bh, const __half* Bl,
                         const float* bias, const float* res,
                         float* C, __half* Ch, __half* Cl,
                         int M, int N, int K, int flags) {
    dim3 grid(N / 64, M / 64);
    hgemm_k<<<grid, 128, HG_SMEM>>>(Ah, Al, Bh, Bl, bias, res, C, Ch, Cl, M, N, K, flags);
}

extern "C" void kernel_launch(void* const* d_in, const int* in_sizes, int n_in,
                              void* d_out, int out_size) {
    const int* idx       = (const int*)d_in[0];
    const int* targets   = (const int*)d_in[1];
    const float* tok_emb = (const float*)d_in[2];
    const float* pos_emb = (const float*)d_in[3];
    const float* wq      = (const float*)d_in[4];
    const float* wk      = (const float*)d_in[5];
    const float* wv      = (const float*)d_in[6];
    const float* wproj   = (const float*)d_in[7];
    const float* bproj   = (const float*)d_in[8];
    const float* w1      = (const float*)d_in[9];
    const float* b1      = (const float*)d_in[10];
    const float* w2      = (const float*)d_in[11];
    const float* b2      = (const float*)d_in[12];
    const float* ln1_g   = (const float*)d_in[13];
    const float* ln1_b   = (const float*)d_in[14];
    const float* ln2_g   = (const float*)d_in[15];
    const float* ln2_b   = (const float*)d_in[16];
    const float* lnf_g   = (const float*)d_in[17];
    const float* lnf_b   = (const float*)d_in[18];
    const float* lm_w    = (const float*)d_in[19];
    const float* lm_b    = (const float*)d_in[20];
    float* out = (float*)d_out;

    float *px, *pqkv;
    __half *pt1h, *pt1l, *poh, *pol, *pt2h, *pt2l;
    __half *pwqkvh, *pwqkvl, *pwph, *pwpl, *pw1h, *pw1l, *pw2h, *pw2l;
    cudaGetSymbolAddress((void**)&px, g_x);
    cudaGetSymbolAddress((void**)&pqkv, g_qkv);
    cudaGetSymbolAddress((void**)&pt1h, g_t1h);
    cudaGetSymbolAddress((void**)&pt1l, g_t1l);
    cudaGetSymbolAddress((void**)&poh, g_oh);
    cudaGetSymbolAddress((void**)&pol, g_ol);
    cudaGetSymbolAddress((void**)&pt2h, g_t2h);
    cudaGetSymbolAddress((void**)&pt2l, g_t2l);
    cudaGetSymbolAddress((void**)&pwqkvh, g_wqkvh);
    cudaGetSymbolAddress((void**)&pwqkvl, g_wqkvl);
    cudaGetSymbolAddress((void**)&pwph, g_wph);
    cudaGetSymbolAddress((void**)&pwpl, g_wpl);
    cudaGetSymbolAddress((void**)&pw1h, g_w1h);
    cudaGetSymbolAddress((void**)&pw1l, g_w1l);
    cudaGetSymbolAddress((void**)&pw2h, g_w2h);
    cudaGetSymbolAddress((void**)&pw2l, g_w2l);

    cudaFuncSetAttribute(lmhead_k, cudaFuncAttributeMaxDynamicSharedMemorySize, LM_SMEM);
    cudaFuncSetAttribute(hgemm_k, cudaFuncAttributeMaxDynamicSharedMemorySize, HG_SMEM);

    embed_k<<<BT, DD>>>(idx, tok_emb, pos_emb);
    cvtwqkv_k<<<(LL * 384 * DD + 255) / 256, 256>>>(wq, wk, wv);
    cvtw_k<<<dim3(DD / 32, DD / 32, LL), dim3(32, 8)>>>(wproj, pwph, pwpl, DD, DD);
    cvtw_k<<<dim3(DFF / 32, DD / 32, LL), dim3(32, 8)>>>(w1, pw1h, pw1l, DD, DFF);
    cvtw_k<<<dim3(DD / 32, DFF / 32, LL), dim3(32, 8)>>>(w2, pw2h, pw2l, DFF, DD);
    cvtb_k<<<dim3(NPAD / 32, 4), dim3(32, 8)>>>(lm_w);

    for (int l = 0; l < LL; l++) {
        // LN1 -> split
        lnsplit_k<<<BT, DD>>>(px, ln1_g + l * DD, ln1_b + l * DD, pt1h, pt1l);
        // QKV (fp32 out)
        launch_hgemm(pt1h, pt1l,
                     pwqkvh + (size_t)l * 384 * DD, pwqkvl + (size_t)l * 384 * DD,
                     nullptr, nullptr, pqkv, nullptr, nullptr, BT, 384, DD, 0);
        attn_k<<<BB * HH, TT>>>();
        // proj + bias + residual -> x (fp32)
        launch_hgemm(poh, pol,
                     pwph + (size_t)l * DD * DD, pwpl + (size_t)l * DD * DD,
                     bproj + l * DD, px, px, nullptr, nullptr, BT, DD, DD, 1 | 4);
        // LN2 -> split
        lnsplit_k<<<BT, DD>>>(px, ln2_g + l * DD, ln2_b + l * DD, pt1h, pt1l);
        // MLP1 (bias+relu, fp16 hi/lo out)
        launch_hgemm(pt1h, pt1l,
                     pw1h + (size_t)l * DFF * DD, pw1l + (size_t)l * DFF * DD,
                     b1 + l * DFF, nullptr, nullptr, pt2h, pt2l, BT, DFF, DD, 1 | 2 | 8);
        // MLP2 + bias + residual -> x (fp32), K=512
        launch_hgemm(pt2h, pt2l,
                     pw2h + (size_t)l * DD * DFF, pw2l + (size_t)l * DD * DFF,
                     b2 + l * DD, px, px, nullptr, nullptr, BT, DD, DFF, 1 | 4);
    }

    // final LN -> split (lmhead consumes hi)
    lnsplit_k<<<BT, DD>>>(px, lnf_g, lnf_b, pt1h, pt1l);

    dim3 lgrid(BT / 128, NBLK);
    lmhead_k<<<lgrid, 256, LM_SMEM>>>(lm_b, out);

    nllred_k<<<BT, 128>>>(out, targets);
    if (out_size > BT * VV) {
        loss_k<<<1, 256>>>(out + (size_t)BT * VV);
    }
}

// round 17
// speedup vs baseline: 1.0306x; 1.0306x over previous
#include <cuda_runtime.h>
#include <cuda_bf16.h>
#include <cuda_fp16.h>
#include <math.h>
#include <stdint.h>

#define BB 32
#define TT 128
#define DD 128
#define HH 8
#define HD 16
#define LL 4
#define VV 50257
#define BT (BB * TT)       // 4096
#define DFF (4 * DD)       // 512
#define NBLK 393                 // ceil(VV / 128)
#define NPAD (NBLK * 128)        // 50304

// ---------------- scratch ----------------
__device__ float g_x[BT * DD];
__device__ float g_qkv[BT * 384];
__device__ float g_part[(size_t)BT * NBLK];
__device__ float g_nll[BT];
__device__ __half g_t1h[BT * DD],  g_t1l[BT * DD];    // LN outputs
__device__ __half g_oh[BT * DD],   g_ol[BT * DD];     // attn output
__device__ __half g_t2h[BT * DFF], g_t2l[BT * DFF];   // mlp hidden
__device__ __half g_bh[(size_t)NPAD * DD];
// body weights, n-major [N][K] fp16 hi/lo
__device__ __half g_wqkvh[LL * 384 * DD], g_wqkvl[LL * 384 * DD];
__device__ __half g_wph[LL * DD * DD],   g_wpl[LL * DD * DD];
__device__ __half g_w1h[LL * DFF * DD],  g_w1l[LL * DFF * DD];
__device__ __half g_w2h[LL * DD * DFF],  g_w2l[LL * DD * DFF];

// ---------------- helpers ----------------
__device__ __forceinline__ uint32_t smem_u32(const void* p) {
    uint32_t a;
    asm("{ .reg .u64 t; cvta.to.shared.u64 t, %1; cvt.u32.u64 %0, t; }" : "=r"(a) : "l"(p));
    return a;
}
__device__ __forceinline__ void mma16816(float* c, const uint32_t* a,
                                         uint32_t b0, uint32_t b1) {
    asm volatile(
        "mma.sync.aligned.m16n8k16.row.col.f32.f16.f16.f32 "
        "{%0,%1,%2,%3}, {%4,%5,%6,%7}, {%8,%9}, {%0,%1,%2,%3};"
        : "+f"(c[0]), "+f"(c[1]), "+f"(c[2]), "+f"(c[3])
        : "r"(a[0]), "r"(a[1]), "r"(a[2]), "r"(a[3]), "r"(b0), "r"(b1));
}
__device__ __forceinline__ void ldsm4(uint32_t* r, uint32_t addr) {
    asm volatile("ldmatrix.sync.aligned.m8n8.x4.shared.b16 {%0,%1,%2,%3}, [%4];"
                 : "=r"(r[0]), "=r"(r[1]), "=r"(r[2]), "=r"(r[3]) : "r"(addr));
}
__device__ __forceinline__ void stcs(float* p, float v) {
    asm volatile("st.global.cs.f32 [%0], %1;" :: "l"(p), "f"(v) : "memory");
}

// ---------------- embedding ----------------
__global__ void embed_k(const int* __restrict__ idx,
                        const float* __restrict__ tok,
                        const float* __restrict__ pos) {
    int m = blockIdx.x;
    int d = threadIdx.x;
    int t = m & (TT - 1);
    g_x[m * DD + d] = tok[(size_t)idx[m] * DD + d] + pos[t * DD + d];
}

// ---------------- qkv weights [L,H,D,HD] -> n-major [L][384][128] fp16 hi/lo ----------------
__global__ void cvtwqkv_k(const float* __restrict__ wq,
                          const float* __restrict__ wk,
                          const float* __restrict__ wv) {
    int o = blockIdx.x * 256 + threadIdx.x;
    if (o >= LL * 384 * DD) return;
    int l = o / (384 * DD);
    int rem = o % (384 * DD);
    int n = rem >> 7, d = rem & 127;
    int which = n >> 7;
    int nn = n & 127;
    int h = nn >> 4, e = nn & 15;
    const float* W = (which == 0) ? wq : (which == 1) ? wk : wv;
    float x = W[(((size_t)l * HH + h) * DD + d) * HD + e];
    __half hi = __float2half(x);
    g_wqkvh[o] = hi;
    g_wqkvl[o] = __float2half(x - __half2float(hi));
}

// ---------------- generic weight transpose-convert: W[l][K][N] -> [l][N][K] hi/lo ----------------
__global__ void cvtw_k(const float* __restrict__ W, __half* __restrict__ oh,
                       __half* __restrict__ ol, int K, int N) {
    __shared__ float t[32][33];
    int l = blockIdx.z;
    const float* Wl = W + (size_t)l * K * N;
    __half* ohl = oh + (size_t)l * N * K;
    __half* oll = ol + (size_t)l * N * K;
    int n0 = blockIdx.x * 32, k0 = blockIdx.y * 32;
    int tx = threadIdx.x, ty = threadIdx.y;  // 32 x 8
    for (int i = ty; i < 32; i += 8)
        t[i][tx] = Wl[(size_t)(k0 + i) * N + n0 + tx];
    __syncthreads();
    for (int i = ty; i < 32; i += 8) {
        int n = n0 + i, k = k0 + tx;
        float x = t[tx][i];
        __half hi = __float2half(x);
        ohl[(size_t)n * K + k] = hi;
        oll[(size_t)n * K + k] = __float2half(x - __half2float(hi));
    }
}

// ---------------- LN fused with fp16 hi/lo split (used once, layer-0 entry) ----------------
__global__ void lnsplit_k(const float* __restrict__ in,
                          const float* __restrict__ gam, const float* __restrict__ bet,
                          __half* __restrict__ oh, __half* __restrict__ ol) {
    __shared__ float red[4];
    int m = blockIdx.x, d = threadIdx.x;
    int i = m * DD + d;
    float x = in[i];
    float s = x;
#pragma unroll
    for (int o = 16; o > 0; o >>= 1) s += __shfl_xor_sync(0xffffffffu, s, o);
    if ((d & 31) == 0) red[d >> 5] = s;
    __syncthreads();
    float mean = (red[0] + red[1] + red[2] + red[3]) * (1.0f / DD);
    __syncthreads();
    float c = x - mean;
    float cs = c * c;
#pragma unroll
    for (int o = 16; o > 0; o >>= 1) cs += __shfl_xor_sync(0xffffffffu, cs, o);
    if ((d & 31) == 0) red[d >> 5] = cs;
    __syncthreads();
    float var = (red[0] + red[1] + red[2] + red[3]) * (1.0f / DD);
    float y = c * rsqrtf(var + 1e-5f) * gam[d] + bet[d];
    __half hi = __float2half(y);
    oh[i] = hi;
    ol[i] = __float2half(y - __half2float(hi));
}

// ---------------- attention (fp32 in, fp16 hi/lo out) ----------------
__global__ void attn_k() {
    int b = blockIdx.x / HH;
    int h = blockIdx.x % HH;
    int t = threadIdx.x;
    __shared__ float ks[TT][HD];
    __shared__ float vs[TT][HD];
    const float* rowp = g_qkv + (size_t)(b * TT + t) * 384 + h * HD;
#pragma unroll
    for (int e = 0; e < HD; e++) {
        ks[t][e] = rowp[128 + e];
        vs[t][e] = rowp[256 + e];
    }
    __syncthreads();
    float q[HD];
#pragma unroll
    for (int e = 0; e < HD; e++) q[e] = rowp[e];

    const float scale = 0.08838834764831845f;  // 1/sqrt(128)
    float mrun = -1e30f, lrun = 0.0f;
    float acc[HD];
#pragma unroll
    for (int e = 0; e < HD; e++) acc[e] = 0.0f;
    for (int s = 0; s <= t; s++) {
        float d = 0.0f;
#pragma unroll
        for (int e = 0; e < HD; e++) d += q[e] * ks[s][e];
        d *= scale;
        float mn = fmaxf(mrun, d);
        float corr = __expf(mrun - mn);
        float p = __expf(d - mn);
        lrun = lrun * corr + p;
#pragma unroll
        for (int e = 0; e < HD; e++) acc[e] = acc[e] * corr + p * vs[s][e];
        mrun = mn;
    }
    float inv = 1.0f / lrun;
    size_t base = (size_t)(b * TT + t) * DD + h * HD;
#pragma unroll
    for (int e = 0; e < HD; e += 2) {
        float v0 = acc[e] * inv, v1 = acc[e + 1] * inv;
        __half h0 = __float2half(v0), h1 = __float2half(v1);
        *(__half2*)&g_oh[base + e] = __halves2half2(h0, h1);
        *(__half2*)&g_ol[base + e] = __halves2half2(
            __float2half(v0 - __half2float(h0)), __float2half(v1 - __half2float(h1)));
    }
}

// ---------------- HMMA body GEMM: 64x64 tile, 4 warps, fp16 hi/lo 3-term ----------------
// flags: 1=bias, 2=relu, 8=fp16 hi/lo out (else fp32 out)
#define HG_AH 0
#define HG_AL (HG_AH + 17408)
#define HG_BH (HG_AL + 17408)
#define HG_BL (HG_BH + 17408)
#define HG_SMEM (HG_BL + 17408)       // 69632 bytes

__global__ void __launch_bounds__(128) hgemm_k(
    const __half* __restrict__ Agh, const __half* __restrict__ Agl,
    const __half* __restrict__ Bh, const __half* __restrict__ Bl,
    const float* __restrict__ bias,
    float* __restrict__ C, __half* __restrict__ Ch, __half* __restrict__ Cl,
    int M, int N, int K, int flags) {
    extern __shared__ __align__(16) char smem[];
    __half* Ahs = (__half*)(smem + HG_AH);
    __half* Als = (__half*)(smem + HG_AL);
    __half* Bhs = (__half*)(smem + HG_BH);
    __half* Bls = (__half*)(smem + HG_BL);
    uint32_t sb = smem_u32(smem);

    int tid = threadIdx.x, wid = tid >> 5, lane = tid & 31;
    int bm0 = blockIdx.y * 64, bn0 = blockIdx.x * 64;
    int wm = (wid >> 1) * 32, wn = (wid & 1) * 32;
    int g = lane >> 2, t4 = lane & 3;

    float acc[2][4][4];
#pragma unroll
    for (int i = 0; i < 2; i++)
#pragma unroll
        for (int j = 0; j < 4; j++)
#pragma unroll
            for (int q = 0; q < 4; q++) acc[i][j][q] = 0.0f;

    int lr = lane & 15, lk = lane >> 4;
    uint32_t aHb = sb + HG_AH + (uint32_t)((wm + lr) * 272 + lk * 16);
    uint32_t aLb = sb + HG_AL + (uint32_t)((wm + lr) * 272 + lk * 16);
    uint32_t bHb = sb + HG_BH + (uint32_t)((wn + lr) * 272 + lk * 16);
    uint32_t bLb = sb + HG_BL + (uint32_t)((wn + lr) * 272 + lk * 16);

    for (int kc = 0; kc < K; kc += 128) {
        if (kc) __syncthreads();
        {
            const uint4* ahp = (const uint4*)Agh;
            const uint4* alp = (const uint4*)Agl;
            const uint4* bhp = (const uint4*)Bh;
            const uint4* blp = (const uint4*)Bl;
            int krow = K >> 3, kco = kc >> 3;
            for (int i = tid; i < 1024; i += 128) {
                int row = i >> 4, cb = i & 15;
                size_t ga = (size_t)(bm0 + row) * krow + kco + cb;
                size_t gb2 = (size_t)(bn0 + row) * krow + kco + cb;
                *(uint4*)&Ahs[row * 136 + cb * 8] = ahp[ga];
                *(uint4*)&Als[row * 136 + cb * 8] = alp[ga];
                *(uint4*)&Bhs[row * 136 + cb * 8] = bhp[gb2];
                *(uint4*)&Bls[row * 136 + cb * 8] = blp[gb2];
            }
        }
        __syncthreads();
#pragma unroll
        for (int ks = 0; ks < 8; ks++) {
            uint32_t off = (uint32_t)ks * 32;
            uint32_t ah0[4], ah1[4], al0[4], al1[4];
            uint32_t bh0[4], bh1[4], bl0[4], bl1[4];
            ldsm4(ah0, aHb + off); ldsm4(ah1, aHb + 16 * 272 + off);
            ldsm4(al0, aLb + off); ldsm4(al1, aLb + 16 * 272 + off);
            ldsm4(bh0, bHb + off); ldsm4(bh1, bHb + 16 * 272 + off);
            ldsm4(bl0, bLb + off); ldsm4(bl1, bLb + 16 * 272 + off);
#pragma unroll
            for (int i = 0; i < 2; i++) {
                const uint32_t* ahi = i ? ah1 : ah0;
                const uint32_t* alo = i ? al1 : al0;
#pragma unroll
                for (int j = 0; j < 4; j++) {
                    const uint32_t* bh = (j < 2) ? bh0 : bh1;
                    const uint32_t* bl = (j < 2) ? bl0 : bl1;
                    uint32_t b0h = bh[j & 1], b1h = bh[(j & 1) + 2];
                    uint32_t b0l = bl[j & 1], b1l = bl[(j & 1) + 2];
                    mma16816(acc[i][j], ahi, b0h, b1h);
                    mma16816(acc[i][j], alo, b0h, b1h);
                    mma16816(acc[i][j], ahi, b0l, b1l);
                }
            }
        }
    }

#pragma unroll
    for (int i = 0; i < 2; i++) {
#pragma unroll
        for (int j = 0; j < 4; j++) {
            int col = bn0 + wn + j * 8 + 2 * t4;
            float bx = 0.0f, by = 0.0f;
            if (flags & 1) { bx = bias[col]; by = bias[col + 1]; }
            int r0 = bm0 + wm + i * 16 + g;
            float2 v0 = make_float2(acc[i][j][0] + bx, acc[i][j][1] + by);
            float2 v1 = make_float2(acc[i][j][2] + bx, acc[i][j][3] + by);
            if (flags & 2) {
                v0.x = fmaxf(v0.x, 0.f); v0.y = fmaxf(v0.y, 0.f);
                v1.x = fmaxf(v1.x, 0.f); v1.y = fmaxf(v1.y, 0.f);
            }
            if (flags & 8) {
                __half h0 = __float2half(v0.x), h1 = __float2half(v0.y);
                *(__half2*)&Ch[(size_t)r0 * N + col] = __halves2half2(h0, h1);
                *(__half2*)&Cl[(size_t)r0 * N + col] = __halves2half2(
                    __float2half(v0.x - __half2float(h0)),
                    __float2half(v0.y - __half2float(h1)));
                __half h2 = __float2half(v1.x), h3 = __float2half(v1.y);
                *(__half2*)&Ch[(size_t)(r0 + 8) * N + col] = __halves2half2(h2, h3);
                *(__half2*)&Cl[(size_t)(r0 + 8) * N + col] = __halves2half2(
                    __float2half(v1.x - __half2float(h2)),
                    __float2half(v1.y - __half2float(h3)));
            } else {
                *(float2*)&C[(size_t)r0 * N + col] = v0;
                *(float2*)&C[(size_t)(r0 + 8) * N + col] = v1;
            }
        }
    }
}

// ---------------- HMMA GEMM + residual + LN + split: 64x128 tile, 8 warps ----------------
// x[M,128] += A@B^T + bias; then LN(x) -> oh/ol.  N fixed = 128, K % 128 == 0.
#define HL_AH 0
#define HL_AL (HL_AH + 17408)       // A: 64 rows
#define HL_BH (HL_AL + 17408)       // B: 128 rows
#define HL_BL (HL_BH + 34816)
#define HL_GB (HL_BL + 34816)       // 256 floats
#define HL_SMEM (HL_GB + 1024)      // 105472 bytes

__global__ void __launch_bounds__(256) hgemm_ln_k(
    const __half* __restrict__ Agh, const __half* __restrict__ Agl,
    const __half* __restrict__ Bh, const __half* __restrict__ Bl,
    const float* __restrict__ bias,
    const float* __restrict__ gam, const float* __restrict__ bet,
    float* __restrict__ X, __half* __restrict__ oh, __half* __restrict__ ol,
    int K) {
    extern __shared__ __align__(16) char smem[];
    __half* Ahs = (__half*)(smem + HL_AH);
    __half* Als = (__half*)(smem + HL_AL);
    __half* Bhs = (__half*)(smem + HL_BH);
    __half* Bls = (__half*)(smem + HL_BL);
    float* gb = (float*)(smem + HL_GB);
    uint32_t sb = smem_u32(smem);

    int tid = threadIdx.x, wid = tid >> 5, lane = tid & 31;
    int bm0 = blockIdx.x * 64;
    int wm = (wid >> 2) * 32, wn = (wid & 3) * 32;
    int g = lane >> 2, t4 = lane & 3;

    gb[tid] = (tid < 128) ? gam[tid] : bet[tid - 128];

    float acc[2][4][4];
#pragma unroll
    for (int i = 0; i < 2; i++)
#pragma unroll
        for (int j = 0; j < 4; j++)
#pragma unroll
            for (int q = 0; q < 4; q++) acc[i][j][q] = 0.0f;

    int lr = lane & 15, lk = lane >> 4;
    uint32_t aHb = sb + HL_AH + (uint32_t)((wm + lr) * 272 + lk * 16);
    uint32_t aLb = sb + HL_AL + (uint32_t)((wm + lr) * 272 + lk * 16);
    uint32_t bHb = sb + HL_BH + (uint32_t)((wn + lr) * 272 + lk * 16);
    uint32_t bLb = sb + HL_BL + (uint32_t)((wn + lr) * 272 + lk * 16);

    for (int kc = 0; kc < K; kc += 128) {
        if (kc) __syncthreads();
        {
            const uint4* ahp = (const uint4*)Agh;
            const uint4* alp = (const uint4*)Agl;
            const uint4* bhp = (const uint4*)Bh;
            const uint4* blp = (const uint4*)Bl;
            int krow = K >> 3, kco = kc >> 3;
            for (int i = tid; i < 1024; i += 256) {
                int row = i >> 4, cb = i & 15;
                size_t ga = (size_t)(bm0 + row) * krow + kco + cb;
                *(uint4*)&Ahs[row * 136 + cb * 8] = ahp[ga];
                *(uint4*)&Als[row * 136 + cb * 8] = alp[ga];
            }
            for (int i = tid; i < 2048; i += 256) {
                int row = i >> 4, cb = i & 15;
                size_t gb2 = (size_t)row * krow + kco + cb;   // bn0 = 0
                *(uint4*)&Bhs[row * 136 + cb * 8] = bhp[gb2];
                *(uint4*)&Bls[row * 136 + cb * 8] = blp[gb2];
            }
        }
        __syncthreads();
#pragma unroll
        for (int ks = 0; ks < 8; ks++) {
            uint32_t off = (uint32_t)ks * 32;
            uint32_t ah0[4], ah1[4], al0[4], al1[4];
            uint32_t bh0[4], bh1[4], bl0[4], bl1[4];
            ldsm4(ah0, aHb + off); ldsm4(ah1, aHb + 16 * 272 + off);
            ldsm4(al0, aLb + off); ldsm4(al1, aLb + 16 * 272 + off);
            ldsm4(bh0, bHb + off); ldsm4(bh1, bHb + 16 * 272 + off);
            ldsm4(bl0, bLb + off); ldsm4(bl1, bLb + 16 * 272 + off);
#pragma unroll
            for (int i = 0; i < 2; i++) {
                const uint32_t* ahi = i ? ah1 : ah0;
                const uint32_t* alo = i ? al1 : al0;
#pragma unroll
                for (int j = 0; j < 4; j++) {
                    const uint32_t* bh = (j < 2) ? bh0 : bh1;
                    const uint32_t* bl = (j < 2) ? bl0 : bl1;
                    uint32_t b0h = bh[j & 1], b1h = bh[(j & 1) + 2];
                    uint32_t b0l = bl[j & 1], b1l = bl[(j & 1) + 2];
                    mma16816(acc[i][j], ahi, b0h, b1h);
                    mma16816(acc[i][j], alo, b0h, b1h);
                    mma16816(acc[i][j], ahi, b0l, b1l);
                }
            }
        }
    }
    __syncthreads();

    // epilogue: x += acc + bias; write x; stage x into smem (reuses A region)
    float* stage = (float*)smem;   // 64 rows x 136 floats = 34816 bytes
#pragma unroll
    for (int i = 0; i < 2; i++) {
#pragma unroll
        for (int j = 0; j < 4; j++) {
            int col = wn + j * 8 + 2 * t4;
            float bx = bias[col], by = bias[col + 1];
            int lr0 = wm + i * 16 + g;
            int r0 = bm0 + lr0;
            float2 r = *(const float2*)&X[(size_t)r0 * DD + col];
            float2 v0 = make_float2(acc[i][j][0] + bx + r.x, acc[i][j][1] + by + r.y);
            r = *(const float2*)&X[(size_t)(r0 + 8) * DD + col];
            float2 v1 = make_float2(acc[i][j][2] + bx + r.x, acc[i][j][3] + by + r.y);
            *(float2*)&X[(size_t)r0 * DD + col] = v0;
            *(float2*)&X[(size_t)(r0 + 8) * DD + col] = v1;
            *(float2*)&stage[lr0 * 136 + col] = v0;
            *(float2*)&stage[(lr0 + 8) * 136 + col] = v1;
        }
    }
    __syncthreads();

    // LN pass: warp wid handles rows wid*8 .. wid*8+7; lane covers 4 cols
#pragma unroll
    for (int rr = 0; rr < 8; rr++) {
        int lrow = wid * 8 + rr;
        float4 v = *(const float4*)&stage[lrow * 136 + lane * 4];
        float s = v.x + v.y + v.z + v.w;
        float s2 = v.x * v.x + v.y * v.y + v.z * v.z + v.w * v.w;
#pragma unroll
        for (int o = 16; o > 0; o >>= 1) {
            s += __shfl_xor_sync(0xffffffffu, s, o);
            s2 += __shfl_xor_sync(0xffffffffu, s2, o);
        }
        float mean = s * (1.0f / DD);
        float rstd = rsqrtf(s2 * (1.0f / DD) - mean * mean + 1e-5f);
        size_t base = (size_t)(bm0 + lrow) * DD + lane * 4;
        float y0 = (v.x - mean) * rstd * gb[lane * 4 + 0] + gb[128 + lane * 4 + 0];
        float y1 = (v.y - mean) * rstd * gb[lane * 4 + 1] + gb[128 + lane * 4 + 1];
        float y2 = (v.z - mean) * rstd * gb[lane * 4 + 2] + gb[128 + lane * 4 + 2];
        float y3 = (v.w - mean) * rstd * gb[lane * 4 + 3] + gb[128 + lane * 4 + 3];
        __half h0 = __float2half(y0), h1 = __float2half(y1);
        __half h2 = __float2half(y2), h3 = __float2half(y3);
        *(__half2*)&oh[base] = __halves2half2(h0, h1);
        *(__half2*)&oh[base + 2] = __halves2half2(h2, h3);
        *(__half2*)&ol[base] = __halves2half2(
            __float2half(y0 - __half2float(h0)), __float2half(y1 - __half2float(h1)));
        *(__half2*)&ol[base + 2] = __halves2half2(
            __float2half(y2 - __half2float(h2)), __float2half(y3 - __half2float(h3)));
    }
}

// lm_w [128, V] -> transposed padded [NPAD, 128] fp16 (n-major)
__global__ void cvtb_k(const float* __restrict__ lm_w) {
    __shared__ float t[32][33];
    int n0 = blockIdx.x * 32, k0 = blockIdx.y * 32;
    int tx = threadIdx.x, ty = threadIdx.y;  // 32 x 8
    for (int i = ty; i < 32; i += 8) {
        int n = n0 + tx, k = k0 + i;
        t[i][tx] = (n < VV) ? lm_w[(size_t)k * VV + n] : 0.0f;
    }
    __syncthreads();
    for (int i = ty; i < 32; i += 8) {
        int n = n0 + i, k = k0 + tx;
        g_bh[(size_t)n * DD + k] = __float2half(t[tx][i]);
    }
}

// ---------------- HMMA LM head (pure fp16, ldmatrix, staged coalesced epilogue) ----------------
#define PADH 136
#define ROWB (PADH * 2)                    // 272 bytes per row
#define AH_OFF 0
#define BH_OFF (128 * ROWB)                // 34816
#define BIAS_OFF (2 * 128 * ROWB)          // 69632
#define LM_SMEM (BIAS_OFF + 128 * 4)       // 70144

__global__ void __launch_bounds__(256, 3) lmhead_k(
    const float* __restrict__ bias, float* __restrict__ C) {
    extern __shared__ __align__(16) char smem[];
    uint32_t smem_base = smem_u32(smem);
    int tid = threadIdx.x;
    int wid = tid >> 5;
    int lane = tid & 31;
    int g = lane >> 2;
    int t4 = lane & 3;
    int bm0 = blockIdx.x * 128;
    int bn0 = blockIdx.y * 128;
    int wm = (wid >> 1) * 32;
    int wn = (wid & 1) * 64;

    {
        const uint4* gah = (const uint4*)g_t1h;
        const uint4* gbh = (const uint4*)g_bh;
#pragma unroll
        for (int i = tid; i < 2048; i += 256) {
            int row = i >> 4, cb = i & 15;
            uint32_t so = (uint32_t)(row * ROWB + cb * 16);
            *(uint4*)(smem + AH_OFF + so) = gah[(size_t)(bm0 + row) * 16 + cb];
            *(uint4*)(smem + BH_OFF + so) = gbh[(size_t)(bn0 + row) * 16 + cb];
        }
        float* bs = (float*)(smem + BIAS_OFF);
        if (tid < 128) {
            int c = bn0 + tid;
            bs[tid] = (c < VV) ? bias[c] : 0.0f;
        }
    }
    __syncthreads();

    float acc[2][8][4];
#pragma unroll
    for (int i = 0; i < 2; i++)
#pragma unroll
        for (int j = 0; j < 8; j++)
#pragma unroll
            for (int q = 0; q < 4; q++) acc[i][j][q] = 0.0f;

    int lr = lane & 15;
    int lk = lane >> 4;
    uint32_t abase = smem_base + AH_OFF + (uint32_t)((wm + lr) * ROWB + lk * 16);
    uint32_t bbase[4];
#pragma unroll
    for (int jp = 0; jp < 4; jp++)
        bbase[jp] = smem_base + BH_OFF + (uint32_t)((wn + jp * 16 + lr) * ROWB + lk * 16);

#pragma unroll
    for (int ks = 0; ks < 8; ks++) {
        uint32_t off = (uint32_t)ks * 32;
        uint32_t a0[4], a1[4];
        ldsm4(a0, abase + off);
        ldsm4(a1, abase + (uint32_t)(16 * ROWB) + off);
#pragma unroll
        for (int jp = 0; jp < 4; jp++) {
            uint32_t r[4];
            ldsm4(r, bbase[jp] + off);
            mma16816(acc[0][2 * jp],     a0, r[0], r[2]);
            mma16816(acc[0][2 * jp + 1], a0, r[1], r[3]);
            mma16816(acc[1][2 * jp],     a1, r[0], r[2]);
            mma16816(acc[1][2 * jp + 1], a1, r[1], r[3]);
        }
    }

    __syncthreads();
    float* stage = (float*)smem;  // 128 rows x 136 floats = 69632 bytes
#pragma unroll
    for (int i = 0; i < 2; i++) {
#pragma unroll
        for (int half = 0; half < 2; half++) {
            int r = wm + i * 16 + half * 8 + g;
#pragma unroll
            for (int j = 0; j < 8; j++) {
                int c = wn + j * 8 + 2 * t4;
                *(float2*)&stage[r * 136 + c] =
                    make_float2(acc[i][j][half * 2], acc[i][j][half * 2 + 1]);
            }
        }
    }
    __syncthreads();

    const float* bs = (const float*)(smem + BIAS_OFF);
    for (int rr = 0; rr < 16; rr++) {
        int r = wid * 16 + rr;
        int grow = bm0 + r;
        float* crow = C + (size_t)grow * VV + bn0;
        float s = 0.0f;
#pragma unroll
        for (int p = 0; p < 4; p++) {
            int col = p * 32 + lane;
            float v = stage[r * 136 + col] + bs[col];
            if (bn0 + col < VV) {
                stcs(crow + col, v);
                s += __expf(v);
            }
        }
#pragma unroll
        for (int o = 16; o > 0; o >>= 1) s += __shfl_xor_sync(0xffffffffu, s, o);
        if (lane == 0) g_part[(size_t)grow * NBLK + blockIdx.y] = s;
    }
}

// ---------------- NLL from partials ----------------
__global__ void nllred_k(const float* __restrict__ logits, const int* __restrict__ tgt) {
    int r = blockIdx.x;
    int tid = threadIdx.x;  // 128
    float s = 0.0f;
    for (int c = tid; c < NBLK; c += 128) s += g_part[(size_t)r * NBLK + c];
    __shared__ float red[4];
#pragma unroll
    for (int o = 16; o > 0; o >>= 1) s += __shfl_xor_sync(0xffffffffu, s, o);
    if ((tid & 31) == 0) red[tid >> 5] = s;
    __syncthreads();
    if (tid == 0) {
        float tot = red[0] + red[1] + red[2] + red[3];
        g_nll[r] = logf(tot) - logits[(size_t)r * VV + tgt[r]];
    }
}

__global__ void loss_k(float* __restrict__ out) {
    __shared__ float accs[256];
    float s = 0.0f;
    for (int i = threadIdx.x; i < BT; i += 256) s += g_nll[i];
    accs[threadIdx.x] = s;
    __syncthreads();
    for (int o = 128; o > 0; o >>= 1) {
        if (threadIdx.x < o) accs[threadIdx.x] += accs[threadIdx.x + o];
        __syncthreads();
    }
    if (threadIdx.x == 0) out[0] = accs[0] * (1.0f / BT);
}

// ---------------- host launcher ----------------
static void launch_hgemm(const __half* Ah, const __half* Al,
                         const __half* Bh, const __half* Bl,
                         const float* bias,
                         float* C, __half* Ch, __half* Cl,
                         int M, int N, int K, int flags) {
    dim3 grid(N / 64, M / 64);
    hgemm_k<<<grid, 128, HG_SMEM>>>(Ah, Al, Bh, Bl, bias, C, Ch, Cl, M, N, K, flags);
}

extern "C" void kernel_launch(void* const* d_in, const int* in_sizes, int n_in,
                              void* d_out, int out_size) {
    const int* idx       = (const int*)d_in[0];
    const int* targets   = (const int*)d_in[1];
    const float* tok_emb = (const float*)d_in[2];
    const float* pos_emb = (const float*)d_in[3];
    const float* wq      = (const float*)d_in[4];
    const float* wk      = (const float*)d_in[5];
    const float* wv      = (const float*)d_in[6];
    const float* wproj   = (const float*)d_in[7];
    const float* bproj   = (const float*)d_in[8];
    const float* w1      = (const float*)d_in[9];
    const float* b1      = (const float*)d_in[10];
    const float* w2      = (const float*)d_in[11];
    const float* b2      = (const float*)d_in[12];
    const float* ln1_g   = (const float*)d_in[13];
    const float* ln1_b   = (const float*)d_in[14];
    const float* ln2_g   = (const float*)d_in[15];
    const float* ln2_b   = (const float*)d_in[16];
    const float* lnf_g   = (const float*)d_in[17];
    const float* lnf_b   = (const float*)d_in[18];
    const float* lm_w    = (const float*)d_in[19];
    const float* lm_b    = (const float*)d_in[20];
    float* out = (float*)d_out;

    float *px, *pqkv;
    __half *pt1h, *pt1l, *poh, *pol, *pt2h, *pt2l;
    __half *pwqkvh, *pwqkvl, *pwph, *pwpl, *pw1h, *pw1l, *pw2h, *pw2l;
    cudaGetSymbolAddress((void**)&px, g_x);
    cudaGetSymbolAddress((void**)&pqkv, g_qkv);
    cudaGetSymbolAddress((void**)&pt1h, g_t1h);
    cudaGetSymbolAddress((void**)&pt1l, g_t1l);
    cudaGetSymbolAddress((void**)&poh, g_oh);
    cudaGetSymbolAddress((void**)&pol, g_ol);
    cudaGetSymbolAddress((void**)&pt2h, g_t2h);
    cudaGetSymbolAddress((void**)&pt2l, g_t2l);
    cudaGetSymbolAddress((void**)&pwqkvh, g_wqkvh);
    cudaGetSymbolAddress((void**)&pwqkvl, g_wqkvl);
    cudaGetSymbolAddress((void**)&pwph, g_wph);
    cudaGetSymbolAddress((void**)&pwpl, g_wpl);
    cudaGetSymbolAddress((void**)&pw1h, g_w1h);
    cudaGetSymbolAddress((void**)&pw1l, g_w1l);
    cudaGetSymbolAddress((void**)&pw2h, g_w2h);
    cudaGetSymbolAddress((void**)&pw2l, g_w2l);

    cudaFuncSetAttribute(lmhead_k, cudaFuncAttributeMaxDynamicSharedMemorySize, LM_SMEM);
    cudaFuncSetAttribute(hgemm_k, cudaFuncAttributeMaxDynamicSharedMemorySize, HG_SMEM);
    cudaFuncSetAttribute(hgemm_ln_k, cudaFuncAttributeMaxDynamicSharedMemorySize, HL_SMEM);

    embed_k<<<BT, DD>>>(idx, tok_emb, pos_emb);
    cvtwqkv_k<<<(LL * 384 * DD + 255) / 256, 256>>>(wq, wk, wv);
    cvtw_k<<<dim3(DD / 32, DD / 32, LL), dim3(32, 8)>>>(wproj, pwph, pwpl, DD, DD);
    cvtw_k<<<dim3(DFF / 32, DD / 32, LL), dim3(32, 8)>>>(w1, pw1h, pw1l, DD, DFF);
    cvtw_k<<<dim3(DD / 32, DFF / 32, LL), dim3(32, 8)>>>(w2, pw2h, pw2l, DFF, DD);
    cvtb_k<<<dim3(NPAD / 32, 4), dim3(32, 8)>>>(lm_w);

    // entry LN (layer 0 ln1)
    lnsplit_k<<<BT, DD>>>(px, ln1_g, ln1_b, pt1h, pt1l);

    for (int l = 0; l < LL; l++) {
        // QKV (fp32 out)
        launch_hgemm(pt1h, pt1l,
                     pwqkvh + (size_t)l * 384 * DD, pwqkvl + (size_t)l * 384 * DD,
                     nullptr, pqkv, nullptr, nullptr, BT, 384, DD, 0);
        attn_k<<<BB * HH, TT>>>();
        // proj + bias + residual -> x, then LN2 -> t1 split
        hgemm_ln_k<<<BT / 64, 256, HL_SMEM>>>(
            poh, pol, pwph + (size_t)l * DD * DD, pwpl + (size_t)l * DD * DD,
            bproj + l * DD, ln2_g + l * DD, ln2_b + l * DD,
            px, pt1h, pt1l, DD);
        // MLP1 (bias+relu, fp16 hi/lo out)
        launch_hgemm(pt1h, pt1l,
                     pw1h + (size_t)l * DFF * DD, pw1l + (size_t)l * DFF * DD,
                     b1 + l * DFF, nullptr, pt2h, pt2l, BT, DFF, DD, 1 | 2 | 8);
        // MLP2 + bias + residual -> x, then LN (next ln1, or lnf) -> t1 split
        const float* ng = (l + 1 < LL) ? (ln1_g + (l + 1) * DD) : lnf_g;
        const float* nb = (l + 1 < LL) ? (ln1_b + (l + 1) * DD) : lnf_b;
        hgemm_ln_k<<<BT / 64, 256, HL_SMEM>>>(
            pt2h, pt2l, pw2h + (size_t)l * DD * DFF, pw2l + (size_t)l * DD * DFF,
            b2 + l * DD, ng, nb,
            px, pt1h, pt1l, DFF);
    }

    dim3 lgrid(BT / 128, NBLK);
    lmhead_k<<<lgrid, 256, LM_SMEM>>>(lm_b, out);

    nllred_k<<<BT, 128>>>(out, targets);
    if (out_size > BT * VV) {
        loss_k<<<1, 256>>>(out + (size_t)BT * VV);
    }
}